// round 17
// baseline (speedup 1.0000x reference)
#include <cuda_runtime.h>
#include <cuda_fp16.h>
#include <math.h>
#include <stdint.h>

#define Bz 8
#define Sz 4096
#define Hz 1024
#define Ez 256
#define Kz 64
#define HQ 256
#define NEGV (-1e30f)
#define K4_CHUNKS 8
#define K4_DCH (Hz / K4_CHUNKS)   // 128

// k1 tile geometry (fp16 m16n8k16, ldmatrix frags)
#define K1_BM 128
#define K1_BK 32                  // 16 kpairs per tile
#define K1_NIT (Hz / K1_BK)       // 32
#define K1_APAD 20                // A row stride (half2 words): LDSM-conflict-free
#define K1_BPAD 20                // B n-row stride (half2 words): LDSM-conflict-free
#define K1_AW (K1_BM * K1_APAD)               // 2560 words (single buffer)
#define K1_BW (HQ * K1_BPAD)                  // 5120 words per buffer
#define K1_SMEM_BYTES ((K1_AW + 2 * K1_BW) * 4)   // 51200 B

// ---------------- scratch (static __device__, no allocs) ----------------
__device__ float g_tok_scores[Bz * Sz];        // [B,S]
__device__ float g_mx[Bz * Kz];                // per-(b,k) max
__device__ float g_denom[Bz * Kz];             // per-(b,k) sum of exp
__device__ float g_be[(size_t)Bz * Kz * Hz];   // block_embed [B,K,H] (2 MB)
__device__ float g_blk_score[Bz * Kz];         // stage-2 scores
__device__ float g_part[(size_t)K4_CHUNKS * Bz * Kz * HQ];  // k4 split-K partials (4 MB)
__device__ uint32_t g_w1h[(size_t)HQ * (Hz / 2)];  // tok_w1 as half2, [n][kpair] (0.5 MB)

__device__ __forceinline__ uint32_t h2u(__half2 h) {
    return *reinterpret_cast<uint32_t*>(&h);
}
__device__ __forceinline__ uint32_t smem_u32(const void* p) {
    return (uint32_t)__cvta_generic_to_shared(p);
}
__device__ __forceinline__ void cp16(uint32_t dst_smem, const void* src) {
    asm volatile("cp.async.ca.shared.global [%0], [%1], 16;" :: "r"(dst_smem), "l"(src));
}
__device__ __forceinline__ void ldsm_x4(uint32_t* r, uint32_t saddr) {
    asm volatile("ldmatrix.sync.aligned.m8n8.x4.shared.b16 {%0,%1,%2,%3}, [%4];"
                 : "=r"(r[0]), "=r"(r[1]), "=r"(r[2]), "=r"(r[3]) : "r"(saddr));
}
__device__ __forceinline__ void mma_f16(float* d, const uint32_t* a, const uint32_t* b) {
    asm volatile(
        "mma.sync.aligned.m16n8k16.row.col.f32.f16.f16.f32 "
        "{%0,%1,%2,%3},{%4,%5,%6,%7},{%8,%9},{%0,%1,%2,%3};\n"
        : "+f"(d[0]), "+f"(d[1]), "+f"(d[2]), "+f"(d[3])
        : "r"(a[0]), "r"(a[1]), "r"(a[2]), "r"(a[3]), "r"(b[0]), "r"(b[1]));
}

// ======================================================================
// K0: tok_w1 [K=1024][N=256] fp32 -> g_w1h [N=256][Kpair=512] half2
// ======================================================================
__global__ __launch_bounds__(256)
void k0_w1half(const float* __restrict__ w1) {
    const int idx = blockIdx.x * 256 + threadIdx.x;   // 0..131071
    const int n = idx & 255;
    const int kp = idx >> 8;                          // 0..511
    const float x = w1[(size_t)(2 * kp) * HQ + n];
    const float y = w1[(size_t)(2 * kp + 1) * HQ + n];
    g_w1h[(size_t)n * (Hz / 2) + kp] = h2u(__floats2half2_rn(x, y));
}

// ======================================================================
// K1: tok_scores = tanh(h @ tok_w1 + b1) @ tok_w2 + b2   (fp16 MMA k16)
// BM=128, BN=256, BK=32; 512 thr, 16 warps 4x4; warp tile 32x64.
// B: cp.async double-buffer from pre-converted g_w1h; A: reg-staged cvt.
// Fragment loads via ldmatrix.x4. Epilogue fuses tanh + w2-dot + reduce.
// ======================================================================
__global__ __launch_bounds__(512, 1)
void k1_tok_scores(const float* __restrict__ h,
                   const uint32_t* __restrict__ w1h,
                   const float* __restrict__ b1,
                   const float* __restrict__ w2,
                   const float* __restrict__ b2) {
    extern __shared__ uint32_t dyn[];
    uint32_t* As = dyn;                 // [128][20] half2 words (single buffer)
    uint32_t* Bs = dyn + K1_AW;         // [2][256][20] half2 words
    __shared__ float rowsum[K1_BM];

    const int tid = threadIdx.x;
    const int rowbase = blockIdx.x * K1_BM;
    const int wid = tid >> 5;
    const int lane = tid & 31;
    const int warpM = wid >> 2;         // 0..3
    const int warpN = wid & 3;          // 0..3
    const int g = lane >> 2;            // 0..7
    const int c = lane & 3;             // 0..3
    const int nb = warpN * 64;

    const uint32_t as_sa = smem_u32(As);
    const uint32_t bs_sa = smem_u32(Bs);

    if (tid < K1_BM) rowsum[tid] = 0.f;

    float acc[2][8][4];
#pragma unroll
    for (int mt = 0; mt < 2; mt++)
#pragma unroll
        for (int nt = 0; nt < 8; nt++)
#pragma unroll
            for (int r = 0; r < 4; r++) acc[mt][nt][r] = 0.f;

    // A staging map: row = tid>>3 (0..63, +64), k-float off = (tid&7)*4
    const int a_row = tid >> 3;
    const int a_c4 = (tid & 7) * 4;
    // B cp map: chunk = tid + e*512 -> n = chunk>>2, word = (chunk&3)*4
    const int bn0 = tid >> 2;             // e=0: n 0..127
    const int bw0 = (tid & 3) * 4;

    float4 aR[2];

#define K1_A_LOAD(K0)                                                          \
    do {                                                                       \
        aR[0] = *(const float4*)(h + (size_t)(rowbase + a_row) * Hz + (K0) + a_c4);      \
        aR[1] = *(const float4*)(h + (size_t)(rowbase + a_row + 64) * Hz + (K0) + a_c4); \
    } while (0)

#define K1_A_STS()                                                             \
    do {                                                                       \
        _Pragma("unroll")                                                      \
        for (int e = 0; e < 2; e++) {                                          \
            int row = a_row + e * 64;                                          \
            uint32_t* dst = &As[row * K1_APAD + (a_c4 >> 1)];                  \
            dst[0] = h2u(__floats2half2_rn(aR[e].x, aR[e].y));                 \
            dst[1] = h2u(__floats2half2_rn(aR[e].z, aR[e].w));                 \
        }                                                                      \
    } while (0)

#define K1_B_ISSUE(IT, BUF)                                                    \
    do {                                                                       \
        const uint32_t* src0 = w1h + (size_t)bn0 * (Hz / 2) + (IT) * 16 + bw0; \
        cp16(bs_sa + ((BUF) * K1_BW + bn0 * K1_BPAD + bw0) * 4, src0);         \
        cp16(bs_sa + ((BUF) * K1_BW + (bn0 + 128) * K1_BPAD + bw0) * 4,        \
             src0 + (size_t)128 * (Hz / 2));                                   \
        asm volatile("cp.async.commit_group;");                                \
    } while (0)

    K1_A_LOAD(0);
    K1_B_ISSUE(0, 0);

    for (int it = 0; it < K1_NIT; it++) {
        const int cur = it & 1;
        if (it < K1_NIT - 1) {
            K1_B_ISSUE(it + 1, cur ^ 1);
            asm volatile("cp.async.wait_group 1;");
        } else {
            asm volatile("cp.async.wait_group 0;");
        }
        K1_A_STS();
        __syncthreads();
        if (it < K1_NIT - 1) K1_A_LOAD((it + 1) * K1_BK);

        const uint32_t bbase = bs_sa + (cur * K1_BW) * 4;
#pragma unroll
        for (int ks = 0; ks < 2; ks++) {
            const int kk = ks * 8;      // kpair base for this k16 step
            uint32_t a[2][4];
#pragma unroll
            for (int mt = 0; mt < 2; mt++) {
                const int row = warpM * 32 + mt * 16 + (lane & 7) + ((lane >> 3) & 1) * 8;
                const int word = kk + ((lane >> 4) << 2);
                ldsm_x4(a[mt], as_sa + (row * K1_APAD + word) * 4);
            }
#pragma unroll
            for (int ntp = 0; ntp < 4; ntp++) {
                uint32_t bfr[4];
                const int nrow = nb + ntp * 16 + (lane & 7) + (lane >> 4) * 8;
                const int word = kk + (((lane >> 3) & 1) << 2);
                ldsm_x4(bfr, bbase + (nrow * K1_BPAD + word) * 4);
#pragma unroll
                for (int mt = 0; mt < 2; mt++) {
                    mma_f16(acc[mt][2 * ntp], a[mt], &bfr[0]);
                    mma_f16(acc[mt][2 * ntp + 1], a[mt], &bfr[2]);
                }
            }
        }
        __syncthreads();   // all reads done before smem refilled
    }
#undef K1_A_LOAD
#undef K1_A_STS
#undef K1_B_ISSUE

    // epilogue: row score = sum_col tanh(acc + b1[col]) * w2[col]
#pragma unroll
    for (int mt = 0; mt < 2; mt++) {
#pragma unroll
        for (int half = 0; half < 2; half++) {
            float p = 0.f;
#pragma unroll
            for (int nt = 0; nt < 8; nt++) {
                const int col0 = nb + nt * 8 + c * 2;
                const float v0 = acc[mt][nt][half * 2 + 0] + __ldg(&b1[col0]);
                const float v1 = acc[mt][nt][half * 2 + 1] + __ldg(&b1[col0 + 1]);
                p += tanhf(v0) * __ldg(&w2[col0]) + tanhf(v1) * __ldg(&w2[col0 + 1]);
            }
            p += __shfl_xor_sync(0xffffffffu, p, 1);
            p += __shfl_xor_sync(0xffffffffu, p, 2);
            if (c == 0)
                atomicAdd(&rowsum[warpM * 32 + mt * 16 + half * 8 + g], p);
        }
    }
    __syncthreads();
    if (tid < K1_BM)
        g_tok_scores[rowbase + tid] = rowsum[tid] + b2[0];
}

// ======================================================================
// K2: per-(b,k) segment max & sum-of-exp over contiguous token range
// ======================================================================
__global__ __launch_bounds__(128)
void k2_seg_stats(const int* __restrict__ mask, const int* __restrict__ bnd) {
    const int bk = blockIdx.x;
    const int b = bk >> 6, k = bk & 63;
    int start = __ldg(&bnd[b * Kz + k]);
    int end = (k == Kz - 1) ? Sz : __ldg(&bnd[b * Kz + k + 1]);
    start = max(0, min(start, Sz));
    end = max(start, min(end, Sz));
    const float* sc = g_tok_scores + b * Sz;
    const int* mk = mask + b * Sz;
    const int tid = threadIdx.x;

    float mx = NEGV;
    for (int s = start + tid; s < end; s += 128)
        if (__ldg(&mk[s]) == 1) mx = fmaxf(mx, sc[s]);
    __shared__ float red[4];
#pragma unroll
    for (int off = 16; off > 0; off >>= 1)
        mx = fmaxf(mx, __shfl_xor_sync(0xffffffffu, mx, off));
    if ((tid & 31) == 0) red[tid >> 5] = mx;
    __syncthreads();
    mx = fmaxf(fmaxf(red[0], red[1]), fmaxf(red[2], red[3]));

    float sum = 0.f;
    for (int s = start + tid; s < end; s += 128)
        if (__ldg(&mk[s]) == 1) sum += expf(sc[s] - mx);
    __shared__ float red2[4];
#pragma unroll
    for (int off = 16; off > 0; off >>= 1)
        sum += __shfl_xor_sync(0xffffffffu, sum, off);
    if ((tid & 31) == 0) red2[tid >> 5] = sum;
    __syncthreads();
    if (tid == 0) {
        g_mx[bk] = mx;
        g_denom[bk] = red2[0] + red2[1] + red2[2] + red2[3];
    }
}

// ======================================================================
// K3: block_embed[b,k,:] = sum_s w[s] * h[b,s,:]   (segmented)
// ======================================================================
__global__ __launch_bounds__(256)
void k3_block_embed(const float* __restrict__ h,
                    const int* __restrict__ mask,
                    const int* __restrict__ bnd) {
    const int bk = blockIdx.x;
    const int b = bk >> 6, k = bk & 63;
    int start = __ldg(&bnd[b * Kz + k]);
    int end = (k == Kz - 1) ? Sz : __ldg(&bnd[b * Kz + k + 1]);
    start = max(0, min(start, Sz));
    end = max(start, min(end, Sz));
    const float mx = g_mx[bk];
    const float den = g_denom[bk];
    const float inv = (den > 0.f) ? 1.f / fmaxf(den, 1e-30f) : 0.f;
    const int tid = threadIdx.x;

    const float* sc = g_tok_scores + b * Sz;
    const int* mk = mask + b * Sz;
    const float* hb = h + (size_t)b * Sz * Hz;

    __shared__ float wts[128];
    float4 acc = make_float4(0.f, 0.f, 0.f, 0.f);

    for (int cs = start; cs < end; cs += 128) {
        const int n = min(128, end - cs);
        if (tid < 128) {
            int s = cs + tid;
            float w = 0.f;
            if (s < end && __ldg(&mk[s]) == 1) w = expf(sc[s] - mx) * inv;
            wts[tid] = w;
        }
        __syncthreads();
        for (int i = 0; i < n; i++) {
            float w = wts[i];
            if (w != 0.f) {
                float4 hv = *(const float4*)(hb + (size_t)(cs + i) * Hz + tid * 4);
                acc.x = fmaf(w, hv.x, acc.x);
                acc.y = fmaf(w, hv.y, acc.y);
                acc.z = fmaf(w, hv.z, acc.z);
                acc.w = fmaf(w, hv.w, acc.w);
            }
        }
        __syncthreads();
    }
    *(float4*)(g_be + (size_t)bk * Hz + tid * 4) = acc;
}

// ======================================================================
// K4a: split-K partial GEMM for blk pre-activations.
// ======================================================================
__global__ __launch_bounds__(256)
void k4a_blk_partial(const float* __restrict__ w1) {
    const int group = blockIdx.x >> 3;       // 0..127
    const int chunk = blockIdx.x & 7;        // 0..7
    const int bk0 = group * 4;
    const int d0 = chunk * K4_DCH;
    const int j = threadIdx.x;

    __shared__ float bes[4][K4_DCH];         // 2 KB
#pragma unroll
    for (int e = 0; e < 2; e++) {
        int idx = j + e * 256;               // 0..511
        int r = idx >> 7, d = idx & 127;
        bes[r][d] = g_be[(size_t)(bk0 + r) * Hz + d0 + d];
    }
    __syncthreads();

    float a0 = 0.f, a1 = 0.f, a2 = 0.f, a3 = 0.f;
    const float* w1c = w1 + (size_t)d0 * HQ + j;
#pragma unroll 8
    for (int dd = 0; dd < K4_DCH; dd++) {
        float w = __ldg(w1c + (size_t)dd * HQ);
        a0 = fmaf(bes[0][dd], w, a0);
        a1 = fmaf(bes[1][dd], w, a1);
        a2 = fmaf(bes[2][dd], w, a2);
        a3 = fmaf(bes[3][dd], w, a3);
    }
    float* p = g_part + (size_t)chunk * (Bz * Kz * HQ) + (size_t)bk0 * HQ + j;
    p[0 * HQ] = a0;
    p[1 * HQ] = a1;
    p[2 * HQ] = a2;
    p[3 * HQ] = a3;
}

// ======================================================================
// K4b: combine partials -> tanh -> w2 dot -> blk score (+ validity)
// ======================================================================
__global__ __launch_bounds__(256)
void k4b_blk_scores(const float* __restrict__ b1,
                    const float* __restrict__ w2,
                    const float* __restrict__ b2) {
    const int bk0 = blockIdx.x * 4;
    const int j = threadIdx.x;
    const float b1j = b1[j], w2j = w2[j];

    float v[4];
#pragma unroll
    for (int r = 0; r < 4; r++) {
        float a = 0.f;
#pragma unroll
        for (int c = 0; c < K4_CHUNKS; c++)
            a += g_part[(size_t)c * (Bz * Kz * HQ) + (size_t)(bk0 + r) * HQ + j];
        v[r] = tanhf(a + b1j) * w2j;
    }

    __shared__ float red[4][8];
    const int lane = j & 31, wid = j >> 5;
#pragma unroll
    for (int r = 0; r < 4; r++) {
        float x = v[r];
#pragma unroll
        for (int off = 16; off > 0; off >>= 1)
            x += __shfl_xor_sync(0xffffffffu, x, off);
        if (lane == 0) red[r][wid] = x;
    }
    __syncthreads();
    if (j < 4) {
        float s = 0.f;
#pragma unroll
        for (int w = 0; w < 8; w++) s += red[j][w];
        s += b2[0];
        int bk = bk0 + j;
        g_blk_score[bk] = (g_denom[bk] > 0.f) ? s : NEGV;
    }
}

// ======================================================================
// K5: per batch: softmax over blocks -> func -> out proj -> L2 normalize
// ======================================================================
__global__ __launch_bounds__(256)
void k5_out(const float* __restrict__ out_w,
            const float* __restrict__ out_b,
            float* __restrict__ out) {
    const int b = blockIdx.x;
    const int tid = threadIdx.x;
    __shared__ float bw[Kz];
    __shared__ float func[Hz];
    __shared__ float red[8];

    if (tid == 0) {
        float mx = NEGV;
        for (int k = 0; k < Kz; k++) mx = fmaxf(mx, g_blk_score[b * Kz + k]);
        float s = 0.f;
        for (int k = 0; k < Kz; k++) {
            float e = expf(g_blk_score[b * Kz + k] - mx);
            bw[k] = e;
            s += e;
        }
        float inv = 1.f / s;
        for (int k = 0; k < Kz; k++) bw[k] *= inv;
    }
    __syncthreads();

    const float* be = g_be + (size_t)b * Kz * Hz;
    float4 acc = make_float4(0.f, 0.f, 0.f, 0.f);
    for (int k = 0; k < Kz; k++) {
        float w = bw[k];
        float4 v = *(const float4*)(be + (size_t)k * Hz + tid * 4);
        acc.x = fmaf(w, v.x, acc.x);
        acc.y = fmaf(w, v.y, acc.y);
        acc.z = fmaf(w, v.z, acc.z);
        acc.w = fmaf(w, v.w, acc.w);
    }
    *(float4*)&func[tid * 4] = acc;
    __syncthreads();

    float o = out_b[tid];
    for (int d = 0; d < Hz; d++)
        o = fmaf(func[d], out_w[(size_t)d * Ez + tid], o);

    float ss = o * o;
    const int lane = tid & 31, wid = tid >> 5;
#pragma unroll
    for (int off = 16; off > 0; off >>= 1)
        ss += __shfl_xor_sync(0xffffffffu, ss, off);
    if (lane == 0) red[wid] = ss;
    __syncthreads();
    float tot = 0.f;
#pragma unroll
    for (int w = 0; w < 8; w++) tot += red[w];
    float nrm = fmaxf(sqrtf(tot), 1e-12f);
    out[b * Ez + tid] = o / nrm;
}

// ======================================================================
extern "C" void kernel_launch(void* const* d_in, const int* in_sizes, int n_in,
                              void* d_out, int out_size) {
    const float* hidden = (const float*)d_in[0];
    const int* mask = (const int*)d_in[1];
    const int* bnd = (const int*)d_in[2];
    const float* tok_w1 = (const float*)d_in[3];
    const float* tok_b1 = (const float*)d_in[4];
    const float* tok_w2 = (const float*)d_in[5];
    const float* tok_b2 = (const float*)d_in[6];
    const float* blk_w1 = (const float*)d_in[7];
    const float* blk_b1 = (const float*)d_in[8];
    const float* blk_w2 = (const float*)d_in[9];
    const float* blk_b2 = (const float*)d_in[10];
    const float* out_w = (const float*)d_in[11];
    const float* out_b = (const float*)d_in[12];
    float* out = (float*)d_out;

    static uint32_t* w1h_ptr = nullptr;
    if (!w1h_ptr) cudaGetSymbolAddress((void**)&w1h_ptr, g_w1h);

    cudaFuncSetAttribute(k1_tok_scores,
                         cudaFuncAttributeMaxDynamicSharedMemorySize,
                         K1_SMEM_BYTES);

    k0_w1half<<<(HQ * Hz / 2) / 256, 256>>>(tok_w1);
    k1_tok_scores<<<(Bz * Sz) / K1_BM, 512, K1_SMEM_BYTES>>>(
        hidden, w1h_ptr, tok_b1, tok_w2, tok_b2);
    k2_seg_stats<<<Bz * Kz, 128>>>(mask, bnd);
    k3_block_embed<<<Bz * Kz, 256>>>(hidden, mask, bnd);
    k4a_blk_partial<<<(Bz * Kz / 4) * K4_CHUNKS, 256>>>(blk_w1);
    k4b_blk_scores<<<Bz * Kz / 4, 256>>>(blk_b1, blk_w2, blk_b2);
    k5_out<<<Bz, 256>>>(out_w, out_b, out);
}